// round 1
// baseline (speedup 1.0000x reference)
#include <cuda_runtime.h>
#include <math.h>

#define TOKENS 4096
#define DMODEL 1024
#define DINNER 2048
#define DSTATE 16
#define SEQL   2048

// Scratch (static device globals — no runtime allocation allowed)
__device__ float g_xz [TOKENS * 2 * DINNER];  // 64MB: [token][e], e<2048 = xi pre-conv, e>=2048 = z
__device__ float g_xi [TOKENS * DINNER];      // 32MB: conv+silu output
__device__ float g_dt [TOKENS * DINNER];      // 32MB: softplus dt per (token, d)
__device__ float g_y  [TOKENS * DINNER];      // 32MB: post-scan gated activations
__device__ float g_dbc[TOKENS * 33];          // x_dbl: [dt_raw(1) | B(16) | C(16)] per token

// ---------------------------------------------------------------------------
// C[M,N] = A[M,K] * B[N,K]^T   (both row-major, "NT" gemm), fp32 SIMT tiled
// BM=BN=128, BK=8, 256 threads, 8x8 per-thread micro tile
// ---------------------------------------------------------------------------
__global__ void sgemm_nt(const float* __restrict__ A, const float* __restrict__ B,
                         float* __restrict__ C, int M, int N, int K) {
    __shared__ float As[8][128];
    __shared__ float Bs[8][128];
    const int tx = threadIdx.x, ty = threadIdx.y;     // (16,16)
    const int tid = ty * 16 + tx;
    const int row0 = blockIdx.y * 128, col0 = blockIdx.x * 128;

    float acc[8][8] = {};
    const int lr = tid >> 1;            // 0..127
    const int lc = (tid & 1) * 4;       // 0 or 4
    const float* Aptr = A + (size_t)(row0 + lr) * K + lc;
    const float* Bptr = B + (size_t)(col0 + lr) * K + lc;

    for (int k0 = 0; k0 < K; k0 += 8) {
        float4 a4 = *(const float4*)(Aptr + k0);
        float4 b4 = *(const float4*)(Bptr + k0);
        As[lc + 0][lr] = a4.x; As[lc + 1][lr] = a4.y;
        As[lc + 2][lr] = a4.z; As[lc + 3][lr] = a4.w;
        Bs[lc + 0][lr] = b4.x; Bs[lc + 1][lr] = b4.y;
        Bs[lc + 2][lr] = b4.z; Bs[lc + 3][lr] = b4.w;
        __syncthreads();
#pragma unroll
        for (int k = 0; k < 8; k++) {
            float4 a0 = *(const float4*)&As[k][ty * 8];
            float4 a1 = *(const float4*)&As[k][ty * 8 + 4];
            float4 b0 = *(const float4*)&Bs[k][tx * 8];
            float4 b1 = *(const float4*)&Bs[k][tx * 8 + 4];
            float ra[8] = {a0.x, a0.y, a0.z, a0.w, a1.x, a1.y, a1.z, a1.w};
            float rb[8] = {b0.x, b0.y, b0.z, b0.w, b1.x, b1.y, b1.z, b1.w};
#pragma unroll
            for (int i = 0; i < 8; i++)
#pragma unroll
                for (int j = 0; j < 8; j++)
                    acc[i][j] += ra[i] * rb[j];
        }
        __syncthreads();
    }
#pragma unroll
    for (int i = 0; i < 8; i++) {
        int r = row0 + ty * 8 + i;
        float4* cp = (float4*)&C[(size_t)r * N + col0 + tx * 8];
        cp[0] = make_float4(acc[i][0], acc[i][1], acc[i][2], acc[i][3]);
        cp[1] = make_float4(acc[i][4], acc[i][5], acc[i][6], acc[i][7]);
    }
}

// ---------------------------------------------------------------------------
// Causal depthwise conv (width 4) + bias + SiLU on first half of xz -> g_xi
// ---------------------------------------------------------------------------
__global__ void conv_silu_k(const float* __restrict__ cw, const float* __restrict__ cb) {
    int idx = blockIdx.x * blockDim.x + threadIdx.x;   // over TOKENS*DINNER
    int d = idx & (DINNER - 1);
    int t = idx >> 11;
    int l = t & (SEQL - 1);
    float w0 = cw[d * 4 + 0], w1 = cw[d * 4 + 1], w2 = cw[d * 4 + 2], w3 = cw[d * 4 + 3];
    float acc = cb[d];
    size_t base = (size_t)t * (2 * DINNER) + d;
    if (l >= 3) acc += g_xz[base - 3 * (size_t)(2 * DINNER)] * w0;
    if (l >= 2) acc += g_xz[base - 2 * (size_t)(2 * DINNER)] * w1;
    if (l >= 1) acc += g_xz[base - 1 * (size_t)(2 * DINNER)] * w2;
    acc += g_xz[base] * w3;
    g_xi[idx] = acc / (1.f + __expf(-acc));   // silu
}

// ---------------------------------------------------------------------------
// x_dbl[t, e] = sum_d xi[t,d] * W_x[e,d]   (33 outputs per token)
// block = 64 tokens, blockDim (33, 8)
// ---------------------------------------------------------------------------
__global__ void xdbl_k(const float* __restrict__ Wx) {
    __shared__ float Xs[64][33];   // padded to avoid bank conflicts
    __shared__ float Ws[33][33];
    const int tx = threadIdx.x, ty = threadIdx.y;   // (33,8)
    const int tid = ty * 33 + tx;
    const int tok0 = blockIdx.x * 64;
    float acc[8] = {};
    for (int k0 = 0; k0 < DINNER; k0 += 32) {
        for (int i = tid; i < 64 * 32; i += 264) {
            int tt = i >> 5, kk = i & 31;
            Xs[tt][kk] = g_xi[(size_t)(tok0 + tt) * DINNER + k0 + kk];
        }
        for (int i = tid; i < 33 * 32; i += 264) {
            int e = i >> 5, kk = i & 31;
            Ws[e][kk] = Wx[(size_t)e * DINNER + k0 + kk];
        }
        __syncthreads();
#pragma unroll
        for (int kk = 0; kk < 32; kk++) {
            float w = Ws[tx][kk];
#pragma unroll
            for (int i = 0; i < 8; i++)
                acc[i] += Xs[ty * 8 + i][kk] * w;
        }
        __syncthreads();
    }
#pragma unroll
    for (int i = 0; i < 8; i++)
        g_dbc[(size_t)(tok0 + ty * 8 + i) * 33 + tx] = acc[i];
}

// ---------------------------------------------------------------------------
// dt[t,d] = softplus(dt_raw[t] * W_dt[d] + b_dt[d])
// ---------------------------------------------------------------------------
__global__ void dt_k(const float* __restrict__ Wdt, const float* __restrict__ bdt) {
    int idx = blockIdx.x * blockDim.x + threadIdx.x;
    int d = idx & (DINNER - 1);
    int t = idx >> 11;
    float u = g_dbc[(size_t)t * 33] * Wdt[d] + bdt[d];
    g_dt[idx] = (u > 20.f) ? u : log1pf(__expf(u));
}

// ---------------------------------------------------------------------------
// Selective scan: one 16-lane group per (b,d) channel; 16 channels per block.
// Chunks of 64 timesteps staged through smem. Output includes +D*xi and
// silu(z) gating, written to g_y.
// ---------------------------------------------------------------------------
__global__ void scan_k(const float* __restrict__ A_log, const float* __restrict__ Dvec) {
    __shared__ float sB[64][16], sC[64][16];
    __shared__ float sX[64][16], sZ[64][16], sDT[64][16], sY[64][16];
    const int tid = threadIdx.x;          // 256
    const int dd = tid >> 4, n = tid & 15;
    const int b = blockIdx.y;
    const int d0 = blockIdx.x * 16;
    const int d = d0 + dd;

    const float a  = -__expf(A_log[d * DSTATE + n]);
    const float Dd = Dvec[d];
    float h = 0.f;

    for (int c = 0; c < SEQL / 64; c++) {
        const int tok0 = b * SEQL + c * 64;
        for (int i = tid; i < 64 * 33; i += 256) {
            int tt = i / 33, e = i - tt * 33;
            float v = g_dbc[(size_t)(tok0 + tt) * 33 + e];
            if (e >= 17)     sC[tt][e - 17] = v;
            else if (e >= 1) sB[tt][e - 1]  = v;
        }
        for (int i = tid; i < 64 * 16; i += 256) {
            int tt = i >> 4, q = i & 15;
            sX[tt][q]  = g_xi[(size_t)(tok0 + tt) * DINNER + d0 + q];
            sDT[tt][q] = g_dt[(size_t)(tok0 + tt) * DINNER + d0 + q];
            sZ[tt][q]  = g_xz[(size_t)(tok0 + tt) * (2 * DINNER) + DINNER + d0 + q];
        }
        __syncthreads();
#pragma unroll 4
        for (int t = 0; t < 64; t++) {
            float dtv = sDT[t][dd];
            float xv  = sX[t][dd];
            float dA  = __expf(dtv * a);
            h = dA * h + (dtv * sB[t][n]) * xv;
            float p = h * sC[t][n];
            p += __shfl_xor_sync(0xffffffffu, p, 8);
            p += __shfl_xor_sync(0xffffffffu, p, 4);
            p += __shfl_xor_sync(0xffffffffu, p, 2);
            p += __shfl_xor_sync(0xffffffffu, p, 1);
            if (n == 0) {
                float zv = sZ[t][dd];
                sY[t][dd] = (p + Dd * xv) * (zv / (1.f + __expf(-zv)));
            }
        }
        __syncthreads();
        for (int i = tid; i < 64 * 16; i += 256) {
            int tt = i >> 4, q = i & 15;
            g_y[(size_t)(tok0 + tt) * DINNER + d0 + q] = sY[tt][q];
        }
        __syncthreads();
    }
}

// ---------------------------------------------------------------------------
extern "C" void kernel_launch(void* const* d_in, const int* in_sizes, int n_in,
                              void* d_out, int out_size) {
    const float* x     = (const float*)d_in[0];
    const float* W_in  = (const float*)d_in[1];
    const float* convw = (const float*)d_in[2];
    const float* convb = (const float*)d_in[3];
    const float* W_x   = (const float*)d_in[4];
    const float* W_dt  = (const float*)d_in[5];
    const float* b_dt  = (const float*)d_in[6];
    const float* A_log = (const float*)d_in[7];
    const float* Dv    = (const float*)d_in[8];
    const float* W_out = (const float*)d_in[9];
    float* out = (float*)d_out;

    float *xz, *y;
    cudaGetSymbolAddress((void**)&xz, g_xz);
    cudaGetSymbolAddress((void**)&y,  g_y);

    dim3 bgemm(16, 16);

    // 1) xz = x @ W_in^T   [4096 x 4096], K=1024
    sgemm_nt<<<dim3(4096 / 128, TOKENS / 128), bgemm>>>(x, W_in, xz, TOKENS, 4096, DMODEL);

    // 2) causal depthwise conv + silu -> g_xi
    conv_silu_k<<<(TOKENS * DINNER) / 256, 256>>>(convw, convb);

    // 3) x_dbl = xi @ W_x^T -> g_dbc
    xdbl_k<<<TOKENS / 64, dim3(33, 8)>>>(W_x);

    // 4) dt = softplus(dt_raw * W_dt + b_dt) -> g_dt
    dt_k<<<(TOKENS * DINNER) / 256, 256>>>(W_dt, b_dt);

    // 5) selective scan (+D*xi, *silu(z)) -> g_y
    scan_k<<<dim3(DINNER / 16, 2), 256>>>(A_log, Dv);

    // 6) out = y @ W_out^T   [4096 x 1024], K=2048
    sgemm_nt<<<dim3(DMODEL / 128, TOKENS / 128), bgemm>>>(y, W_out, out, TOKENS, DMODEL, DINNER);
}

// round 2
// speedup vs baseline: 2.7658x; 2.7658x over previous
#include <cuda_runtime.h>
#include <math.h>
#include <stdint.h>

#define TOKENS 4096
#define DMODEL 1024
#define DINNER 2048
#define DSTATE 16
#define SEQL   2048

// Scratch (static device globals — no runtime allocation allowed)
__device__ float g_xz [TOKENS * 2 * DINNER];  // [token][e], e<2048 = xi pre-conv, e>=2048 = z
__device__ float g_xi [TOKENS * DINNER];      // conv+silu output
__device__ float g_dt [TOKENS * DINNER];      // softplus dt per (token, d)
__device__ float g_y  [TOKENS * DINNER];      // post-scan gated activations
__device__ float g_dbc[TOKENS * 33];          // x_dbl: [dt_raw(1) | B(16) | C(16)] per token

// ---------------------------------------------------------------------------
// TF32 tensor-core GEMM:  C[M,N] = A[M,K] * B[N,K]^T  (row-major A, B)
// BM=BN=128, BK=32, 256 threads (8 warps as 2x4), m16n8k8 frags 4x4 per warp,
// cp.async 2-stage double buffer.
// ---------------------------------------------------------------------------
#define BM 128
#define BN 128
#define BK 32
#define SSTRIDE 36                       // floats per row in smem (16B aligned, conflict-free)
#define TILE_FLOATS (BM * SSTRIDE)       // one operand tile

__device__ __forceinline__ uint32_t f2tf32(float x) {
    uint32_t r;
    asm("cvt.rna.tf32.f32 %0, %1;" : "=r"(r) : "f"(x));
    return r;
}

__device__ __forceinline__ void mma_tf32(float* c, const uint32_t* a, const uint32_t* b) {
    asm volatile(
        "mma.sync.aligned.m16n8k8.row.col.f32.tf32.tf32.f32 "
        "{%0,%1,%2,%3}, {%4,%5,%6,%7}, {%8,%9}, {%0,%1,%2,%3};"
        : "+f"(c[0]), "+f"(c[1]), "+f"(c[2]), "+f"(c[3])
        : "r"(a[0]), "r"(a[1]), "r"(a[2]), "r"(a[3]), "r"(b[0]), "r"(b[1]));
}

__device__ __forceinline__ void cp_async16(void* smem_dst, const void* gmem_src) {
    uint32_t s = (uint32_t)__cvta_generic_to_shared(smem_dst);
    asm volatile("cp.async.cg.shared.global [%0], [%1], 16;" :: "r"(s), "l"(gmem_src));
}

__global__ void __launch_bounds__(256, 2)
tf32_gemm_nt(const float* __restrict__ A, const float* __restrict__ B,
             float* __restrict__ C, int M, int N, int K) {
    extern __shared__ float sm[];
    float* As = sm;                        // [2][BM][SSTRIDE]
    float* Bs = sm + 2 * TILE_FLOATS;      // [2][BN][SSTRIDE]

    const int tid  = threadIdx.x;
    const int wid  = tid >> 5;
    const int lane = tid & 31;
    const int gid  = lane >> 2;           // 0..7
    const int t4   = lane & 3;            // 0..3
    const int wm   = wid & 1;             // 2 warps along M (64 rows each)
    const int wn   = wid >> 1;            // 4 warps along N (32 cols each)
    const int row0 = blockIdx.y * BM;
    const int col0 = blockIdx.x * BN;

    // loader mapping: 4 float4 per thread per operand tile
    const int lm  = tid >> 3;             // 0..31 base row (stride 32 over i)
    const int lk  = (tid & 7) * 4;        // k offset 0..28

    float acc[4][4][4] = {};

    const int niter = K / BK;
    int s = 0;
    // prefetch stage 0
    {
#pragma unroll
        for (int i = 0; i < 4; i++) {
            int m = lm + i * 32;
            cp_async16(&As[m * SSTRIDE + lk], A + (size_t)(row0 + m) * K + lk);
            cp_async16(&Bs[m * SSTRIDE + lk], B + (size_t)(col0 + m) * K + lk);
        }
        asm volatile("cp.async.commit_group;");
    }

    for (int it = 0; it < niter; it++) {
        if (it + 1 < niter) {
            int k0 = (it + 1) * BK;
            int sn = s ^ 1;
#pragma unroll
            for (int i = 0; i < 4; i++) {
                int m = lm + i * 32;
                cp_async16(&As[sn * TILE_FLOATS + m * SSTRIDE + lk],
                           A + (size_t)(row0 + m) * K + k0 + lk);
                cp_async16(&Bs[sn * TILE_FLOATS + m * SSTRIDE + lk],
                           B + (size_t)(col0 + m) * K + k0 + lk);
            }
        }
        asm volatile("cp.async.commit_group;");
        asm volatile("cp.async.wait_group 1;");
        __syncthreads();

        const float* Ab = As + s * TILE_FLOATS;
        const float* Bb = Bs + s * TILE_FLOATS;
#pragma unroll
        for (int kk = 0; kk < 4; kk++) {
            const int cc = kk * 8 + t4;
            uint32_t af[4][4], bf[4][2];
#pragma unroll
            for (int fm = 0; fm < 4; fm++) {
                int r = wm * 64 + fm * 16 + gid;
                af[fm][0] = f2tf32(Ab[r * SSTRIDE + cc]);
                af[fm][1] = f2tf32(Ab[(r + 8) * SSTRIDE + cc]);
                af[fm][2] = f2tf32(Ab[r * SSTRIDE + cc + 4]);
                af[fm][3] = f2tf32(Ab[(r + 8) * SSTRIDE + cc + 4]);
            }
#pragma unroll
            for (int fn = 0; fn < 4; fn++) {
                int nn = wn * 32 + fn * 8 + gid;
                bf[fn][0] = f2tf32(Bb[nn * SSTRIDE + cc]);
                bf[fn][1] = f2tf32(Bb[nn * SSTRIDE + cc + 4]);
            }
#pragma unroll
            for (int fm = 0; fm < 4; fm++)
#pragma unroll
                for (int fn = 0; fn < 4; fn++)
                    mma_tf32(acc[fm][fn], af[fm], bf[fn]);
        }
        __syncthreads();
        s ^= 1;
    }

    // epilogue: c0,c1 at (row, col), (row, col+1); c2,c3 at row+8
#pragma unroll
    for (int fm = 0; fm < 4; fm++) {
        int r = row0 + wm * 64 + fm * 16 + gid;
#pragma unroll
        for (int fn = 0; fn < 4; fn++) {
            int cbase = col0 + wn * 32 + fn * 8 + t4 * 2;
            float2* p0 = (float2*)&C[(size_t)r * N + cbase];
            float2* p1 = (float2*)&C[(size_t)(r + 8) * N + cbase];
            *p0 = make_float2(acc[fm][fn][0], acc[fm][fn][1]);
            *p1 = make_float2(acc[fm][fn][2], acc[fm][fn][3]);
        }
    }
}

// ---------------------------------------------------------------------------
// Causal depthwise conv (width 4) + bias + SiLU on first half of xz -> g_xi
// ---------------------------------------------------------------------------
__global__ void conv_silu_k(const float* __restrict__ cw, const float* __restrict__ cb) {
    int idx = blockIdx.x * blockDim.x + threadIdx.x;   // over TOKENS*DINNER
    int d = idx & (DINNER - 1);
    int t = idx >> 11;
    int l = t & (SEQL - 1);
    float w0 = cw[d * 4 + 0], w1 = cw[d * 4 + 1], w2 = cw[d * 4 + 2], w3 = cw[d * 4 + 3];
    float acc = cb[d];
    size_t base = (size_t)t * (2 * DINNER) + d;
    if (l >= 3) acc += g_xz[base - 3 * (size_t)(2 * DINNER)] * w0;
    if (l >= 2) acc += g_xz[base - 2 * (size_t)(2 * DINNER)] * w1;
    if (l >= 1) acc += g_xz[base - 1 * (size_t)(2 * DINNER)] * w2;
    acc += g_xz[base] * w3;
    g_xi[idx] = acc / (1.f + __expf(-acc));   // silu
}

// ---------------------------------------------------------------------------
// x_dbl[t, e] = sum_d xi[t,d] * W_x[e,d]   (33 outputs per token) — fp32
// ---------------------------------------------------------------------------
__global__ void xdbl_k(const float* __restrict__ Wx) {
    __shared__ float Xs[64][33];
    __shared__ float Ws[33][33];
    const int tx = threadIdx.x, ty = threadIdx.y;   // (33,8)
    const int tid = ty * 33 + tx;
    const int tok0 = blockIdx.x * 64;
    float acc[8] = {};
    for (int k0 = 0; k0 < DINNER; k0 += 32) {
        for (int i = tid; i < 64 * 32; i += 264) {
            int tt = i >> 5, kk = i & 31;
            Xs[tt][kk] = g_xi[(size_t)(tok0 + tt) * DINNER + k0 + kk];
        }
        for (int i = tid; i < 33 * 32; i += 264) {
            int e = i >> 5, kk = i & 31;
            Ws[e][kk] = Wx[(size_t)e * DINNER + k0 + kk];
        }
        __syncthreads();
#pragma unroll
        for (int kk = 0; kk < 32; kk++) {
            float w = Ws[tx][kk];
#pragma unroll
            for (int i = 0; i < 8; i++)
                acc[i] += Xs[ty * 8 + i][kk] * w;
        }
        __syncthreads();
    }
#pragma unroll
    for (int i = 0; i < 8; i++)
        g_dbc[(size_t)(tok0 + ty * 8 + i) * 33 + tx] = acc[i];
}

// ---------------------------------------------------------------------------
// dt[t,d] = softplus(dt_raw[t] * W_dt[d] + b_dt[d])
// ---------------------------------------------------------------------------
__global__ void dt_k(const float* __restrict__ Wdt, const float* __restrict__ bdt) {
    int idx = blockIdx.x * blockDim.x + threadIdx.x;
    int d = idx & (DINNER - 1);
    int t = idx >> 11;
    float u = g_dbc[(size_t)t * 33] * Wdt[d] + bdt[d];
    g_dt[idx] = (u > 20.f) ? u : log1pf(__expf(u));
}

// ---------------------------------------------------------------------------
// Selective scan: one 16-lane group per (b,d) channel; 16 channels per block.
// ---------------------------------------------------------------------------
__global__ void scan_k(const float* __restrict__ A_log, const float* __restrict__ Dvec) {
    __shared__ float sB[64][16], sC[64][16];
    __shared__ float sX[64][16], sZ[64][16], sDT[64][16], sY[64][16];
    const int tid = threadIdx.x;          // 256
    const int dd = tid >> 4, n = tid & 15;
    const int b = blockIdx.y;
    const int d0 = blockIdx.x * 16;
    const int d = d0 + dd;

    const float a  = -__expf(A_log[d * DSTATE + n]);
    const float Dd = Dvec[d];
    float h = 0.f;

    for (int c = 0; c < SEQL / 64; c++) {
        const int tok0 = b * SEQL + c * 64;
        for (int i = tid; i < 64 * 33; i += 256) {
            int tt = i / 33, e = i - tt * 33;
            float v = g_dbc[(size_t)(tok0 + tt) * 33 + e];
            if (e >= 17)     sC[tt][e - 17] = v;
            else if (e >= 1) sB[tt][e - 1]  = v;
        }
        for (int i = tid; i < 64 * 16; i += 256) {
            int tt = i >> 4, q = i & 15;
            sX[tt][q]  = g_xi[(size_t)(tok0 + tt) * DINNER + d0 + q];
            sDT[tt][q] = g_dt[(size_t)(tok0 + tt) * DINNER + d0 + q];
            sZ[tt][q]  = g_xz[(size_t)(tok0 + tt) * (2 * DINNER) + DINNER + d0 + q];
        }
        __syncthreads();
#pragma unroll 4
        for (int t = 0; t < 64; t++) {
            float dtv = sDT[t][dd];
            float xv  = sX[t][dd];
            float dA  = __expf(dtv * a);
            h = dA * h + (dtv * sB[t][n]) * xv;
            float p = h * sC[t][n];
            p += __shfl_xor_sync(0xffffffffu, p, 8);
            p += __shfl_xor_sync(0xffffffffu, p, 4);
            p += __shfl_xor_sync(0xffffffffu, p, 2);
            p += __shfl_xor_sync(0xffffffffu, p, 1);
            if (n == 0) {
                float zv = sZ[t][dd];
                sY[t][dd] = (p + Dd * xv) * (zv / (1.f + __expf(-zv)));
            }
        }
        __syncthreads();
        for (int i = tid; i < 64 * 16; i += 256) {
            int tt = i >> 4, q = i & 15;
            g_y[(size_t)(tok0 + tt) * DINNER + d0 + q] = sY[tt][q];
        }
        __syncthreads();
    }
}

// ---------------------------------------------------------------------------
extern "C" void kernel_launch(void* const* d_in, const int* in_sizes, int n_in,
                              void* d_out, int out_size) {
    const float* x     = (const float*)d_in[0];
    const float* W_in  = (const float*)d_in[1];
    const float* convw = (const float*)d_in[2];
    const float* convb = (const float*)d_in[3];
    const float* W_x   = (const float*)d_in[4];
    const float* W_dt  = (const float*)d_in[5];
    const float* b_dt  = (const float*)d_in[6];
    const float* A_log = (const float*)d_in[7];
    const float* Dv    = (const float*)d_in[8];
    const float* W_out = (const float*)d_in[9];
    float* out = (float*)d_out;

    float *xz, *y;
    cudaGetSymbolAddress((void**)&xz, g_xz);
    cudaGetSymbolAddress((void**)&y,  g_y);

    const int smem_bytes = 4 * TILE_FLOATS * (int)sizeof(float);   // 73728
    cudaFuncSetAttribute(tf32_gemm_nt, cudaFuncAttributeMaxDynamicSharedMemorySize, smem_bytes);

    // 1) xz = x @ W_in^T   [4096 x 4096], K=1024
    tf32_gemm_nt<<<dim3(4096 / BN, TOKENS / BM), 256, smem_bytes>>>(x, W_in, xz, TOKENS, 4096, DMODEL);

    // 2) causal depthwise conv + silu -> g_xi
    conv_silu_k<<<(TOKENS * DINNER) / 256, 256>>>(convw, convb);

    // 3) x_dbl = xi @ W_x^T -> g_dbc  (fp32: feeds exp/softplus in scan)
    xdbl_k<<<TOKENS / 64, dim3(33, 8)>>>(W_x);

    // 4) dt = softplus(dt_raw * W_dt + b_dt) -> g_dt
    dt_k<<<(TOKENS * DINNER) / 256, 256>>>(W_dt, b_dt);

    // 5) selective scan (+D*xi, *silu(z)) -> g_y
    scan_k<<<dim3(DINNER / 16, 2), 256>>>(A_log, Dv);

    // 6) out = y @ W_out^T   [4096 x 1024], K=2048
    tf32_gemm_nt<<<dim3(DMODEL / BN, TOKENS / BM), 256, smem_bytes>>>(y, W_out, out, TOKENS, DMODEL, DINNER);
}

// round 3
// speedup vs baseline: 4.3411x; 1.5696x over previous
#include <cuda_runtime.h>
#include <math.h>
#include <stdint.h>

#define TOKENS 4096
#define DMODEL 1024
#define DINNER 2048
#define DSTATE 16
#define SEQL   2048

// Scratch (static device globals — no runtime allocation allowed)
__device__ float g_xz  [TOKENS * 2 * DINNER];  // [token][e], e<2048 = xi pre-conv, e>=2048 = z
__device__ float g_xi  [TOKENS * DINNER];      // conv+silu output
__device__ float g_y   [TOKENS * DINNER];      // post-scan gated activations
__device__ float g_dbc [TOKENS * 33];          // x_dbl: [dt_raw(1) | B(16) | C(16)] per token
__device__ float g_dbcp[8][TOKENS * 33];       // split-K partials for x_dbl

// ---------------------------------------------------------------------------
// TF32 tensor-core GEMM:  C[M,N] = A[M,K] * B[N,K]^T  (row-major A, B)
// BM=BN=128, BK=32, 256 threads (8 warps as 2x4), m16n8k8 frags 4x4 per warp,
// cp.async 3-stage pipeline.
// ---------------------------------------------------------------------------
#define BM 128
#define BN 128
#define BK 32
#define SSTRIDE 36                       // floats per smem row (16B aligned, conflict-free)
#define TILE_FLOATS (BM * SSTRIDE)       // one operand tile
#define STAGE_FLOATS (2 * TILE_FLOATS)   // A + B per stage

__device__ __forceinline__ uint32_t f2tf32(float x) {
    uint32_t r;
    asm("cvt.rna.tf32.f32 %0, %1;" : "=r"(r) : "f"(x));
    return r;
}

__device__ __forceinline__ void mma_tf32(float* c, const uint32_t* a, const uint32_t* b) {
    asm volatile(
        "mma.sync.aligned.m16n8k8.row.col.f32.tf32.tf32.f32 "
        "{%0,%1,%2,%3}, {%4,%5,%6,%7}, {%8,%9}, {%0,%1,%2,%3};"
        : "+f"(c[0]), "+f"(c[1]), "+f"(c[2]), "+f"(c[3])
        : "r"(a[0]), "r"(a[1]), "r"(a[2]), "r"(a[3]), "r"(b[0]), "r"(b[1]));
}

__device__ __forceinline__ void cp_async16(void* smem_dst, const void* gmem_src) {
    uint32_t s = (uint32_t)__cvta_generic_to_shared(smem_dst);
    asm volatile("cp.async.cg.shared.global [%0], [%1], 16;" :: "r"(s), "l"(gmem_src));
}

__global__ void __launch_bounds__(256, 2)
tf32_gemm_nt(const float* __restrict__ A, const float* __restrict__ B,
             float* __restrict__ C, int M, int N, int K) {
    extern __shared__ float sm[];

    const int tid  = threadIdx.x;
    const int wid  = tid >> 5;
    const int lane = tid & 31;
    const int gid  = lane >> 2;           // 0..7
    const int t4   = lane & 3;            // 0..3
    const int wm   = wid & 1;             // 2 warps along M (64 rows each)
    const int wn   = wid >> 1;            // 4 warps along N (32 cols each)
    const int row0 = blockIdx.y * BM;
    const int col0 = blockIdx.x * BN;

    // loader mapping: 4 float4 per thread per operand tile
    const int lm  = tid >> 3;             // 0..31 base row (stride 32 over i)
    const int lk  = (tid & 7) * 4;        // k offset 0..28

    float acc[4][4][4] = {};

    const int niter = K / BK;

    auto load_stage = [&](int stage, int k0) {
        float* Sa = sm + stage * STAGE_FLOATS;
        float* Sb = Sa + TILE_FLOATS;
#pragma unroll
        for (int i = 0; i < 4; i++) {
            int m = lm + i * 32;
            cp_async16(&Sa[m * SSTRIDE + lk], A + (size_t)(row0 + m) * K + k0 + lk);
            cp_async16(&Sb[m * SSTRIDE + lk], B + (size_t)(col0 + m) * K + k0 + lk);
        }
    };

    // prefetch stages 0 and 1
    load_stage(0, 0);
    asm volatile("cp.async.commit_group;");
    if (niter > 1) load_stage(1, BK);
    asm volatile("cp.async.commit_group;");

    int s = 0;
    for (int it = 0; it < niter; it++) {
        asm volatile("cp.async.wait_group 1;");
        __syncthreads();

        // prefetch stage it+2 into the buffer freed at iter it-1
        if (it + 2 < niter) load_stage((it + 2) % 3, (it + 2) * BK);
        asm volatile("cp.async.commit_group;");

        const float* Ab = sm + s * STAGE_FLOATS;
        const float* Bb = Ab + TILE_FLOATS;
#pragma unroll
        for (int kk = 0; kk < 4; kk++) {
            const int cc = kk * 8 + t4;
            uint32_t af[4][4], bf[4][2];
#pragma unroll
            for (int fm = 0; fm < 4; fm++) {
                int r = wm * 64 + fm * 16 + gid;
                af[fm][0] = f2tf32(Ab[r * SSTRIDE + cc]);
                af[fm][1] = f2tf32(Ab[(r + 8) * SSTRIDE + cc]);
                af[fm][2] = f2tf32(Ab[r * SSTRIDE + cc + 4]);
                af[fm][3] = f2tf32(Ab[(r + 8) * SSTRIDE + cc + 4]);
            }
#pragma unroll
            for (int fn = 0; fn < 4; fn++) {
                int nn = wn * 32 + fn * 8 + gid;
                bf[fn][0] = f2tf32(Bb[nn * SSTRIDE + cc]);
                bf[fn][1] = f2tf32(Bb[nn * SSTRIDE + cc + 4]);
            }
#pragma unroll
            for (int fm = 0; fm < 4; fm++)
#pragma unroll
                for (int fn = 0; fn < 4; fn++)
                    mma_tf32(acc[fm][fn], af[fm], bf[fn]);
        }
        __syncthreads();
        s = (s + 1) % 3;
    }

#pragma unroll
    for (int fm = 0; fm < 4; fm++) {
        int r = row0 + wm * 64 + fm * 16 + gid;
#pragma unroll
        for (int fn = 0; fn < 4; fn++) {
            int cbase = col0 + wn * 32 + fn * 8 + t4 * 2;
            float2* p0 = (float2*)&C[(size_t)r * N + cbase];
            float2* p1 = (float2*)&C[(size_t)(r + 8) * N + cbase];
            *p0 = make_float2(acc[fm][fn][0], acc[fm][fn][1]);
            *p1 = make_float2(acc[fm][fn][2], acc[fm][fn][3]);
        }
    }
}

// ---------------------------------------------------------------------------
// Causal depthwise conv (width 4) + bias + SiLU on first half of xz -> g_xi
// ---------------------------------------------------------------------------
__global__ void conv_silu_k(const float* __restrict__ cw, const float* __restrict__ cb) {
    int idx = blockIdx.x * blockDim.x + threadIdx.x;   // over TOKENS*DINNER
    int d = idx & (DINNER - 1);
    int t = idx >> 11;
    int l = t & (SEQL - 1);
    float w0 = cw[d * 4 + 0], w1 = cw[d * 4 + 1], w2 = cw[d * 4 + 2], w3 = cw[d * 4 + 3];
    float acc = cb[d];
    size_t base = (size_t)t * (2 * DINNER) + d;
    if (l >= 3) acc += g_xz[base - 3 * (size_t)(2 * DINNER)] * w0;
    if (l >= 2) acc += g_xz[base - 2 * (size_t)(2 * DINNER)] * w1;
    if (l >= 1) acc += g_xz[base - 1 * (size_t)(2 * DINNER)] * w2;
    acc += g_xz[base] * w3;
    g_xi[idx] = acc / (1.f + __expf(-acc));   // silu
}

// ---------------------------------------------------------------------------
// x_dbl split-K partials: grid (64, 8); block (33,8) handles 64 tokens,
// K range [by*256, by*256+256). Deterministic reduce in a separate kernel.
// ---------------------------------------------------------------------------
__global__ void xdbl_part_k(const float* __restrict__ Wx) {
    __shared__ float Xs[64][33];
    __shared__ float Ws[33][33];
    const int tx = threadIdx.x, ty = threadIdx.y;   // (33,8)
    const int tid = ty * 33 + tx;
    const int tok0 = blockIdx.x * 64;
    const int kbase = blockIdx.y * 256;
    float acc[8] = {};
    for (int k0 = kbase; k0 < kbase + 256; k0 += 32) {
        for (int i = tid; i < 64 * 32; i += 264) {
            int tt = i >> 5, kk = i & 31;
            Xs[tt][kk] = g_xi[(size_t)(tok0 + tt) * DINNER + k0 + kk];
        }
        for (int i = tid; i < 33 * 32; i += 264) {
            int e = i >> 5, kk = i & 31;
            Ws[e][kk] = Wx[(size_t)e * DINNER + k0 + kk];
        }
        __syncthreads();
#pragma unroll
        for (int kk = 0; kk < 32; kk++) {
            float w = Ws[tx][kk];
#pragma unroll
            for (int i = 0; i < 8; i++)
                acc[i] += Xs[ty * 8 + i][kk] * w;
        }
        __syncthreads();
    }
#pragma unroll
    for (int i = 0; i < 8; i++)
        g_dbcp[blockIdx.y][(size_t)(tok0 + ty * 8 + i) * 33 + tx] = acc[i];
}

__global__ void xdbl_reduce_k() {
    int i = blockIdx.x * blockDim.x + threadIdx.x;
    if (i >= TOKENS * 33) return;
    float s = 0.f;
#pragma unroll
    for (int p = 0; p < 8; p++) s += g_dbcp[p][i];
    g_dbc[i] = s;
}

// ---------------------------------------------------------------------------
// Selective scan. 16 channels per block, 16 state-lanes per channel.
// 32-step chunks. dt softplus computed in staging (no separate dt kernel).
// Per-step shfl-tree replaced by smem partial store + per-chunk reduction.
// ---------------------------------------------------------------------------
#define CH 32                      // chunk timesteps
#define PSTRIDE 17                 // padded [dd][n] stride in sP row

__global__ void __launch_bounds__(256)
scan_k(const float* __restrict__ A_log, const float* __restrict__ Dvec,
       const float* __restrict__ Wdt, const float* __restrict__ bdt) {
    __shared__ float sB[CH][16], sC[CH][16];
    __shared__ float sX[CH][16], sZ[CH][16], sDT[CH][16];
    __shared__ float sP[CH][16 * PSTRIDE];   // [t][dd*17 + n]
    const int tid = threadIdx.x;          // 256
    const int dd = tid >> 4, n = tid & 15;
    const int b = blockIdx.y;
    const int d0 = blockIdx.x * 16;

    const float a  = -__expf(A_log[(d0 + dd) * DSTATE + n]);
    const float wq = Wdt[d0 + n];      // per-thread constants indexed by q = n
    const float bq = bdt[d0 + n];
    const float Dq = Dvec[d0 + n];
    float h = 0.f;

    for (int c = 0; c < SEQL / CH; c++) {
        const int tok0 = b * SEQL + c * CH;
        for (int i = tid; i < CH * 33; i += 256) {
            int tt = i / 33, e = i - tt * 33;
            float v = g_dbc[(size_t)(tok0 + tt) * 33 + e];
            if (e >= 17)     sC[tt][e - 17] = v;
            else if (e >= 1) sB[tt][e - 1]  = v;
        }
        for (int i = tid; i < CH * 16; i += 256) {
            int tt = i >> 4;                 // q == n (stride 256 preserves low 4 bits)
            sX[tt][n] = g_xi[(size_t)(tok0 + tt) * DINNER + d0 + n];
            sZ[tt][n] = g_xz[(size_t)(tok0 + tt) * (2 * DINNER) + DINNER + d0 + n];
            float u = g_dbc[(size_t)(tok0 + tt) * 33] * wq + bq;
            sDT[tt][n] = (u > 20.f) ? u : log1pf(__expf(u));
        }
        __syncthreads();
#pragma unroll
        for (int t = 0; t < CH; t++) {
            float dtv = sDT[t][dd];
            float xv  = sX[t][dd];
            float dA  = __expf(dtv * a);
            h = dA * h + (dtv * sB[t][n]) * xv;
            sP[t][dd * PSTRIDE + n] = h * sC[t][n];
        }
        __syncthreads();
        for (int i = tid; i < CH * 16; i += 256) {
            int tt = i >> 4;                 // channel q == n
            float s = 0.f;
#pragma unroll
            for (int j = 0; j < 16; j++) s += sP[tt][n * PSTRIDE + j];
            float xv = sX[tt][n], zv = sZ[tt][n];
            g_y[(size_t)(tok0 + tt) * DINNER + d0 + n] =
                (s + Dq * xv) * (zv / (1.f + __expf(-zv)));
        }
        __syncthreads();
    }
}

// ---------------------------------------------------------------------------
extern "C" void kernel_launch(void* const* d_in, const int* in_sizes, int n_in,
                              void* d_out, int out_size) {
    const float* x     = (const float*)d_in[0];
    const float* W_in  = (const float*)d_in[1];
    const float* convw = (const float*)d_in[2];
    const float* convb = (const float*)d_in[3];
    const float* W_x   = (const float*)d_in[4];
    const float* W_dt  = (const float*)d_in[5];
    const float* b_dt  = (const float*)d_in[6];
    const float* A_log = (const float*)d_in[7];
    const float* Dv    = (const float*)d_in[8];
    const float* W_out = (const float*)d_in[9];
    float* out = (float*)d_out;

    float *xz, *y;
    cudaGetSymbolAddress((void**)&xz, g_xz);
    cudaGetSymbolAddress((void**)&y,  g_y);

    const int smem_bytes = 3 * STAGE_FLOATS * (int)sizeof(float);   // 110592
    cudaFuncSetAttribute(tf32_gemm_nt, cudaFuncAttributeMaxDynamicSharedMemorySize, smem_bytes);

    // 1) xz = x @ W_in^T   [4096 x 4096], K=1024
    tf32_gemm_nt<<<dim3(4096 / BN, TOKENS / BM), 256, smem_bytes>>>(x, W_in, xz, TOKENS, 4096, DMODEL);

    // 2) causal depthwise conv + silu -> g_xi
    conv_silu_k<<<(TOKENS * DINNER) / 256, 256>>>(convw, convb);

    // 3) x_dbl = xi @ W_x^T (split-K partials + deterministic reduce)
    xdbl_part_k<<<dim3(TOKENS / 64, 8), dim3(33, 8)>>>(W_x);
    xdbl_reduce_k<<<(TOKENS * 33 + 255) / 256, 256>>>();

    // 4) selective scan (softplus folded into staging; +D*xi; *silu(z)) -> g_y
    scan_k<<<dim3(DINNER / 16, 2), 256>>>(A_log, Dv, W_dt, b_dt);

    // 5) out = y @ W_out^T   [4096 x 1024], K=2048
    tf32_gemm_nt<<<dim3(DMODEL / BN, TOKENS / BM), 256, smem_bytes>>>(y, W_out, out, TOKENS, DMODEL, DINNER);
}